// round 4
// baseline (speedup 1.0000x reference)
#include <cuda_runtime.h>
#include <math.h>

#define HDIM   512
#define LWN    32
#define VOCABC 5000
#define MAXLVL 20002
#define MAXCTAS 1024
#define NTOTC  40000
#define NPARC  20000

// ---------------- static device scratch ----------------
__device__ float g_Et[(size_t)VOCABC * HDIM];
__device__ float g_node_h[(size_t)NTOTC * HDIM];
__device__ float g_xe_par[(size_t)NPARC * HDIM];
__device__ float g_Wx[(size_t)NPARC * 3 * HDIM];
__device__ float g_mem[(size_t)NPARC * HDIM];
__device__ float g_zbuf[(size_t)NPARC * HDIM];
__device__ float g_mr[(size_t)NPARC * HDIM];
__device__ int   g_lvl[NTOTC];
__device__ int   g_order[NPARC];
__device__ int   g_lvl_cnt[MAXLVL];
__device__ int   g_lvl_off[MAXLVL + 2];
__device__ int   g_lvl_cur[MAXLVL];
__device__ int   g_maxlvl;
__device__ float g_part[(size_t)MAXCTAS * HDIM];
__device__ unsigned g_bar_cnt1[64 * 32];   // per-group counters, 128B apart
__device__ unsigned g_bar_cnt2;
__device__ unsigned g_bar_gen;

// ---------------- two-level grid barrier (all CTAs co-resident) ----------------
__device__ __forceinline__ void gbar() {
    __syncthreads();
    if (threadIdx.x == 0) {
        __threadfence();
        const unsigned gen = *((volatile unsigned*)&g_bar_gen);
        const int grp  = blockIdx.x >> 4;
        const int ngrp = ((int)gridDim.x + 15) >> 4;
        const int gsz  = min(16, (int)gridDim.x - (grp << 4));
        if (atomicAdd(&g_bar_cnt1[grp * 32], 1u) == (unsigned)(gsz - 1)) {
            g_bar_cnt1[grp * 32] = 0;
            if (atomicAdd(&g_bar_cnt2, 1u) == (unsigned)(ngrp - 1)) {
                g_bar_cnt2 = 0;
                __threadfence();
                *((volatile unsigned*)&g_bar_gen) = gen + 1u;
            }
        }
        while (*((volatile unsigned*)&g_bar_gen) == gen) { __nanosleep(16); }
        __threadfence();
    }
    __syncthreads();
}

__device__ __forceinline__ float sigm(float x) { return 1.f / (1.f + __expf(-x)); }

// packed 2xfp32 FMA (Blackwell FFMA2) — bit-identical to two scalar fmaf
__device__ __forceinline__ void ffma2(float2& d, const float2 a, const float2 b) {
    unsigned long long& dd = reinterpret_cast<unsigned long long&>(d);
    const unsigned long long aa = *reinterpret_cast<const unsigned long long*>(&a);
    const unsigned long long bb = *reinterpret_cast<const unsigned long long*>(&b);
    asm("fma.rn.f32x2 %0, %1, %2, %0;" : "+l"(dd) : "l"(aa), "l"(bb));
}

// shared pool layout (floats): As [2*16*132] | Bs [2*16*136] | rid [128 ints]
#define POOL_AS   0
#define POOL_BS   (2 * 16 * 132)
#define POOL_RID  (POOL_BS + 2 * 16 * 136)
#define POOL_SIZE (POOL_RID + 128)

// ---------------- tiled fp32 GEMM (FFMA2, double-buffered, dup-B) ----------------
// C[i,c] = dot(A[row_i, :512], B[c, :512]); B rows picked from B0/B1/B2 per 512-col band.
// mode 0: g_Wx[p*1536+c] = acc + bias(c)
// mode 1: c<512 -> z=sigm(acc+Wx[c]);  c>=512 -> r=sigm(acc+Wx[512+c']); mr = r*mem
// mode 2: cand=tanh(acc+Wx[1024+c]); node_h[L+p] = z*mem + (1-z)*cand
template<int TM>
__device__ void run_gemm(float* pool, int mode, int M, const int* __restrict__ rowids,
                         const float* __restrict__ Asrc, int Nn,
                         const float* __restrict__ B0, const float* __restrict__ B1,
                         const float* __restrict__ B2,
                         const float* __restrict__ bz, const float* __restrict__ br,
                         const float* __restrict__ bh, int L, int cta, int ncta)
{
    constexpr int MR = TM / 16;   // rows per thread: 8 / 4 / 2
    constexpr int PR = MR / 2;    // row pairs:       4 / 2 / 1
    constexpr int AST = TM + 4;   // As row stride (floats)
    float* AsP = pool + POOL_AS;
    float* BsP = pool + POOL_BS;
    int*   rid = (int*)(pool + POOL_RID);
#define AS_(b,k,m) AsP[((b) * 16 + (k)) * AST + (m)]
#define BS_(b,k,m) BsP[((b) * 16 + (k)) * 136 + (m)]

    const int tid = threadIdx.x;
    const int tx = tid & 15, ty = tid >> 4;
    const int li = tid >> 2;            // 0..63
    const int lk = (tid & 3) << 2;      // 0,4,8,12
    const int nMt = (M + TM - 1) / TM, nNt = Nn >> 6;
    const int nTiles = nMt * nNt;

    for (int tile = cta; tile < nTiles; tile += ncta) {
        const int mt = tile / nNt, nt = tile % nNt;
        const int m0 = mt * TM, n0 = nt << 6;
        __syncthreads();
        if (tid < TM) {
            int rr = m0 + tid;
            rid[tid] = (rr < M) ? (rowids ? rowids[rr] : rr) : -1;
        }
        __syncthreads();

        const float* Bbase = (n0 < 512) ? B0 : ((n0 < 1024) ? B1 : B2);
        const int nb = n0 & 511;
        const int ar0 = (li < TM) ? rid[li] : -1;
        const int ar1 = (TM == 128) ? rid[li + 64] : -1;
        const float* aRow0 = Asrc + (size_t)(ar0 < 0 ? 0 : ar0) * HDIM;
        const float* aRow1 = Asrc + (size_t)(ar1 < 0 ? 0 : ar1) * HDIM;
        const float* bRow  = Bbase + (size_t)(nb + li) * HDIM;

        float2 acc[PR][4];
#pragma unroll
        for (int i = 0; i < PR; i++)
#pragma unroll
            for (int j = 0; j < 4; j++) acc[i][j] = make_float2(0.f, 0.f);

        // prefetch k0 = 0
        float4 rA0 = (ar0 >= 0) ? *(const float4*)(aRow0 + lk) : make_float4(0,0,0,0);
        float4 rA1 = make_float4(0,0,0,0);
        if (TM == 128 && ar1 >= 0) rA1 = *(const float4*)(aRow1 + lk);
        float4 rB = *(const float4*)(bRow + lk);

        int buf = 0;
#pragma unroll 1
        for (int k0 = 0; k0 < HDIM; k0 += 16) {
            // store prefetched regs into smem[buf]
            if (li < TM) {
                AS_(buf, lk+0, li) = rA0.x; AS_(buf, lk+1, li) = rA0.y;
                AS_(buf, lk+2, li) = rA0.z; AS_(buf, lk+3, li) = rA0.w;
            }
            if (TM == 128) {
                AS_(buf, lk+0, 64+li) = rA1.x; AS_(buf, lk+1, 64+li) = rA1.y;
                AS_(buf, lk+2, 64+li) = rA1.z; AS_(buf, lk+3, 64+li) = rA1.w;
            }
            *(float2*)&BS_(buf, lk+0, 2*li) = make_float2(rB.x, rB.x);
            *(float2*)&BS_(buf, lk+1, 2*li) = make_float2(rB.y, rB.y);
            *(float2*)&BS_(buf, lk+2, 2*li) = make_float2(rB.z, rB.z);
            *(float2*)&BS_(buf, lk+3, 2*li) = make_float2(rB.w, rB.w);
            __syncthreads();
            // prefetch next k-step (hidden behind compute)
            if (k0 + 16 < HDIM) {
                if (ar0 >= 0) rA0 = *(const float4*)(aRow0 + k0 + 16 + lk);
                if (TM == 128 && ar1 >= 0) rA1 = *(const float4*)(aRow1 + k0 + 16 + lk);
                rB = *(const float4*)(bRow + k0 + 16 + lk);
            }
#pragma unroll
            for (int kk = 0; kk < 16; kk++) {
                float4 b01 = *(const float4*)&BS_(buf, kk, tx * 8);
                float4 b23 = *(const float4*)&BS_(buf, kk, tx * 8 + 4);
                float2 bb0 = make_float2(b01.x, b01.y);
                float2 bb1 = make_float2(b01.z, b01.w);
                float2 bb2 = make_float2(b23.x, b23.y);
                float2 bb3 = make_float2(b23.z, b23.w);
                float2 a2[PR];
                if (MR == 2) {
                    a2[0] = *(const float2*)&AS_(buf, kk, ty * 2);
                } else {
                    float4 t0 = *(const float4*)&AS_(buf, kk, ty * MR);
                    a2[0] = make_float2(t0.x, t0.y);
                    a2[1] = make_float2(t0.z, t0.w);
                    if (MR == 8) {
                        float4 t1 = *(const float4*)&AS_(buf, kk, ty * MR + 4);
                        a2[2] = make_float2(t1.x, t1.y);
                        a2[3] = make_float2(t1.z, t1.w);
                    }
                }
#pragma unroll
                for (int pr = 0; pr < PR; pr++) {
                    ffma2(acc[pr][0], a2[pr], bb0);
                    ffma2(acc[pr][1], a2[pr], bb1);
                    ffma2(acc[pr][2], a2[pr], bb2);
                    ffma2(acc[pr][3], a2[pr], bb3);
                }
            }
            buf ^= 1;
        }
        // epilogue
#pragma unroll
        for (int pr = 0; pr < PR; pr++) {
#pragma unroll
            for (int h = 0; h < 2; h++) {
                const int lrow = ty * MR + pr * 2 + h;
                const int p = rid[lrow];
                if (p < 0) continue;
#pragma unroll
                for (int j = 0; j < 4; j++) {
                    const int c = n0 + (tx << 2) + j;
                    const float a = h ? acc[pr][j].y : acc[pr][j].x;
                    if (mode == 0) {
                        float bias = (c < 512) ? bz[c] : ((c < 1024) ? br[c-512] : bh[c-1024]);
                        g_Wx[(size_t)p*1536 + c] = a + bias;
                    } else if (mode == 1) {
                        if (c < 512) {
                            g_zbuf[(size_t)p*HDIM + c] = sigm(a + g_Wx[(size_t)p*1536 + c]);
                        } else {
                            const int c2 = c - 512;
                            float r = sigm(a + g_Wx[(size_t)p*1536 + 512 + c2]);
                            g_mr[(size_t)p*HDIM + c2] = r * g_mem[(size_t)p*HDIM + c2];
                        }
                    } else {
                        float cc = tanhf(a + g_Wx[(size_t)p*1536 + 1024 + c]);
                        float z  = g_zbuf[(size_t)p*HDIM + c];
                        float mm = g_mem[(size_t)p*HDIM + c];
                        g_node_h[(size_t)(L + p)*HDIM + c] = z*mm + (1.f - z)*cc;
                    }
                }
            }
        }
    }
#undef AS_
#undef BS_
}

// ---------------- 5-layer star attention, one warp per (parent, half) ----------------
__device__ void attn_phase(int off, int B, const int* __restrict__ tree)
{
    const int lane = threadIdx.x & 31;
    const int gw = (blockIdx.x * blockDim.x + threadIdx.x) >> 5;
    const int nw = (gridDim.x * blockDim.x) >> 5;
    for (int item = gw; item < 2 * B; item += nw) {
        const int p = g_order[off + (item >> 1)];
        const int half = item & 1;
        const int cbase = half * 256 + lane * 8;
        float v[4][8];
        unsigned mb = 0u;
#pragma unroll
        for (int i = 0; i < 4; i++) {
            int c = tree[p * 4 + i];
            if (c >= 0) {
                mb |= (1u << i);
                const float4* hp = (const float4*)(g_node_h + (size_t)c*HDIM + cbase);
                float4 a = hp[0], b = hp[1];
                v[i][0]=a.x; v[i][1]=a.y; v[i][2]=a.z; v[i][3]=a.w;
                v[i][4]=b.x; v[i][5]=b.y; v[i][6]=b.z; v[i][7]=b.w;
            } else {
#pragma unroll
                for (int j = 0; j < 8; j++) v[i][j] = 0.f;
            }
        }
        const float denom = (float)max(__popc(mb), 1);
#pragma unroll 1
        for (int layer = 0; layer < 5; layer++) {
            float s[4][4];
#pragma unroll
            for (int i = 0; i < 4; i++)
#pragma unroll
                for (int k = 0; k < 4; k++) {
                    float t = 0.f;
#pragma unroll
                    for (int j = 0; j < 8; j++) t += v[i][j] * v[k][j];
                    t += __shfl_xor_sync(0xffffffffu, t, 1);
                    t += __shfl_xor_sync(0xffffffffu, t, 2);
                    t += __shfl_xor_sync(0xffffffffu, t, 4);
                    s[i][k] = ((mb >> k) & 1u) ? t * 0.125f : -1e9f;
                }
#pragma unroll
            for (int i = 0; i < 4; i++) {
                float mx = fmaxf(fmaxf(s[i][0], s[i][1]), fmaxf(s[i][2], s[i][3]));
                float e0 = __expf(s[i][0]-mx), e1 = __expf(s[i][1]-mx);
                float e2 = __expf(s[i][2]-mx), e3 = __expf(s[i][3]-mx);
                float inv = 1.f / (e0+e1+e2+e3);
                s[i][0]=e0*inv; s[i][1]=e1*inv; s[i][2]=e2*inv; s[i][3]=e3*inv;
            }
            float o[4][8];
#pragma unroll
            for (int i = 0; i < 4; i++)
#pragma unroll
                for (int j = 0; j < 8; j++)
                    o[i][j] = s[i][0]*v[0][j] + s[i][1]*v[1][j]
                            + s[i][2]*v[2][j] + s[i][3]*v[3][j];
#pragma unroll
            for (int i = 0; i < 4; i++)
#pragma unroll
                for (int j = 0; j < 8; j++) v[i][j] = o[i][j];
        }
        float m8[8];
#pragma unroll
        for (int j = 0; j < 8; j++) {
            float t = 0.f;
#pragma unroll
            for (int i = 0; i < 4; i++) if ((mb >> i) & 1u) t += v[i][j];
            m8[j] = t / denom;
        }
        float4* mp = (float4*)(g_mem + (size_t)p*HDIM + cbase);
        mp[0] = make_float4(m8[0], m8[1], m8[2], m8[3]);
        mp[1] = make_float4(m8[4], m8[5], m8[6], m8[7]);
    }
}

// ---------------- the persistent kernel ----------------
extern "C" __global__ void __launch_bounds__(256, 2) star_all(
    const float* __restrict__ xw, const int* __restrict__ xi, const int* __restrict__ tree,
    const float* __restrict__ Ebu,
    const float* __restrict__ Wz, const float* __restrict__ Uz, const float* __restrict__ bz,
    const float* __restrict__ Wr, const float* __restrict__ Ur, const float* __restrict__ br,
    const float* __restrict__ Wh, const float* __restrict__ Uh, const float* __restrict__ bh,
    const float* __restrict__ Wout, const float* __restrict__ bout,
    float* __restrict__ out, int N, int P)
{
    __shared__ __align__(16) float s_pool[POOL_SIZE];
    const int L = N - P;
    const int tid = threadIdx.x;
    const int gtid = blockIdx.x * blockDim.x + tid;
    const int nthreads = gridDim.x * blockDim.x;

    // ---- P0: init levels/counters + transpose embedding ----
    for (int n = gtid; n < N; n += nthreads) g_lvl[n] = (n < L) ? 0 : -1;
    for (int i = gtid; i < MAXLVL; i += nthreads) g_lvl_cnt[i] = 0;
    if (gtid == 0) g_maxlvl = 0;
    {
        const int tot = HDIM * VOCABC;
        for (int e = gtid; e < tot; e += nthreads) {
            int h = e / VOCABC, v = e - h * VOCABC;
            g_Et[(size_t)v * HDIM + h] = Ebu[e];
        }
    }
    gbar();

    // ---- P1: embedding xe = sum_l Et[idx]*w (preloaded idx/w -> high MLP) ----
    {
        const int c0 = tid, c1 = tid + 256;
        for (int n = blockIdx.x; n < N; n += gridDim.x) {
            const int4*   ip4 = (const int4*)(xi + (size_t)n * LWN);
            const float4* wp4 = (const float4*)(xw + (size_t)n * LWN);
            float a0 = 0.f, a1 = 0.f;
#pragma unroll
            for (int q = 0; q < 8; q++) {
                int4 iv = ip4[q]; float4 wv = wp4[q];
                const float* e0 = g_Et + (size_t)iv.x * HDIM;
                const float* e1 = g_Et + (size_t)iv.y * HDIM;
                const float* e2 = g_Et + (size_t)iv.z * HDIM;
                const float* e3 = g_Et + (size_t)iv.w * HDIM;
                a0 += e0[c0]*wv.x + e1[c0]*wv.y + e2[c0]*wv.z + e3[c0]*wv.w;
                a1 += e0[c1]*wv.x + e1[c1]*wv.y + e2[c1]*wv.z + e3[c1]*wv.w;
            }
            float* dst = (n < L) ? (g_node_h + (size_t)n * HDIM)
                                 : (g_xe_par + (size_t)(n - L) * HDIM);
            dst[c0] = a0; dst[c1] = a1;
        }
    }
    gbar();

    // ---- P2: level discovery (dataflow spin, deps point to lower ids) ----
    for (int p = gtid; p < P; p += nthreads) {
        int lv = 0;
#pragma unroll
        for (int i = 0; i < 4; i++) {
            int c = tree[p * 4 + i];
            if (c >= 0) {
                int cl;
                if (c < L) cl = 0;
                else {
                    while ((cl = *((volatile int*)&g_lvl[c])) < 0) { __nanosleep(32); }
                }
                lv = max(lv, cl);
            }
        }
        lv += 1;
        *((volatile int*)&g_lvl[L + p]) = lv;
        atomicAdd(&g_lvl_cnt[lv], 1);
        atomicMax(&g_maxlvl, lv);
    }
    gbar();

    // ---- P3: Wx GEMM on blocks>0; block0 thread0 does level prefix sum ----
    if (blockIdx.x == 0) {
        if (tid == 0) {
            int ml = g_maxlvl;
            int run = 0;
            for (int lv = 1; lv <= ml; lv++) {
                g_lvl_off[lv] = run;
                g_lvl_cur[lv] = run;
                run += g_lvl_cnt[lv];
            }
            g_lvl_off[ml + 1] = run;
        }
        __syncthreads();
    } else {
        run_gemm<128>(s_pool, 0, P, nullptr, g_xe_par, 1536, Wz, Wr, Wh,
                      bz, br, bh, L, blockIdx.x - 1, gridDim.x - 1);
    }
    gbar();

    // ---- P4: scatter parents into level-ordered array ----
    for (int p = gtid; p < P; p += nthreads) {
        int lv = g_lvl[L + p];
        int slot = atomicAdd(&g_lvl_cur[lv], 1);
        g_order[slot] = p;
    }
    gbar();

    // ---- level loop ----
    const int maxlvl = g_maxlvl;
    for (int lv = 1; lv <= maxlvl; lv++) {
        const int off = g_lvl_off[lv];
        const int cnt = g_lvl_off[lv + 1] - off;
        if (cnt == 0) continue;
        attn_phase(off, cnt, tree);
        gbar();
        if (cnt >= 2048) {
            run_gemm<128>(s_pool, 1, cnt, g_order + off, g_mem, 1024, Uz, Ur, nullptr,
                          nullptr, nullptr, nullptr, L, blockIdx.x, gridDim.x);
            gbar();
            run_gemm<128>(s_pool, 2, cnt, g_order + off, g_mr, 512, Uh, nullptr, nullptr,
                          nullptr, nullptr, nullptr, L, blockIdx.x, gridDim.x);
        } else if (cnt >= 768) {
            run_gemm<64>(s_pool, 1, cnt, g_order + off, g_mem, 1024, Uz, Ur, nullptr,
                         nullptr, nullptr, nullptr, L, blockIdx.x, gridDim.x);
            gbar();
            run_gemm<64>(s_pool, 2, cnt, g_order + off, g_mr, 512, Uh, nullptr, nullptr,
                         nullptr, nullptr, nullptr, L, blockIdx.x, gridDim.x);
        } else {
            run_gemm<32>(s_pool, 1, cnt, g_order + off, g_mem, 1024, Uz, Ur, nullptr,
                         nullptr, nullptr, nullptr, L, blockIdx.x, gridDim.x);
            gbar();
            run_gemm<32>(s_pool, 2, cnt, g_order + off, g_mr, 512, Uh, nullptr, nullptr,
                         nullptr, nullptr, nullptr, L, blockIdx.x, gridDim.x);
        }
        gbar();
    }

    // ---- P5: per-CTA column max over parents ----
    {
        const int rpc = (P + gridDim.x - 1) / gridDim.x;
        const int r0 = blockIdx.x * rpc;
        const int r1 = min(r0 + rpc, P);
        const int c0 = tid, c1 = tid + 256;
        float v0 = -3.4e38f, v1 = -3.4e38f;
        for (int r = r0; r < r1; r++) {
            const float* row = g_node_h + (size_t)(L + r) * HDIM;
            v0 = fmaxf(v0, row[c0]);
            v1 = fmaxf(v1, row[c1]);
        }
        g_part[(size_t)blockIdx.x * HDIM + c0] = v0;
        g_part[(size_t)blockIdx.x * HDIM + c1] = v1;
    }
    gbar();

    // ---- P6: block 0 finishes: reduce, matvec, softmax ----
    if (blockIdx.x == 0) {
        float* sfinal = s_pool;          // reuse pool
        float* slog   = s_pool + HDIM;
        const int c0 = tid, c1 = tid + 256;
        float v0 = -3.4e38f, v1 = -3.4e38f;
        for (int g = 0; g < (int)gridDim.x; g++) {
            v0 = fmaxf(v0, g_part[(size_t)g * HDIM + c0]);
            v1 = fmaxf(v1, g_part[(size_t)g * HDIM + c1]);
        }
        sfinal[c0] = v0; sfinal[c1] = v1;
        __syncthreads();
        const int w = tid >> 5, lane = tid & 31;
        if (w < 4) {
            float t = 0.f;
#pragma unroll
            for (int j = 0; j < 16; j++) {
                int c = lane * 16 + j;
                t += Wout[w * HDIM + c] * sfinal[c];
            }
#pragma unroll
            for (int d = 16; d > 0; d >>= 1) t += __shfl_xor_sync(0xffffffffu, t, d);
            if (lane == 0) slog[w] = t + bout[w];
        }
        __syncthreads();
        if (tid == 0) {
            float mx = fmaxf(fmaxf(slog[0], slog[1]), fmaxf(slog[2], slog[3]));
            float e0 = __expf(slog[0]-mx), e1 = __expf(slog[1]-mx);
            float e2 = __expf(slog[2]-mx), e3 = __expf(slog[3]-mx);
            float inv = 1.f / (e0+e1+e2+e3);
            out[0] = e0*inv; out[1] = e1*inv; out[2] = e2*inv; out[3] = e3*inv;
        }
    }
}

extern "C" void kernel_launch(void* const* d_in, const int* in_sizes, int n_in,
                              void* d_out, int out_size) {
    const float* xw   = (const float*)d_in[0];
    const int*   xi   = (const int*)  d_in[1];
    const int*   tree = (const int*)  d_in[2];
    const float* Ebu  = (const float*)d_in[3];
    const float* Wz   = (const float*)d_in[4];
    const float* Uz   = (const float*)d_in[5];
    const float* bz   = (const float*)d_in[6];
    const float* Wr   = (const float*)d_in[7];
    const float* Ur   = (const float*)d_in[8];
    const float* br   = (const float*)d_in[9];
    const float* Wh   = (const float*)d_in[10];
    const float* Uh   = (const float*)d_in[11];
    const float* bh   = (const float*)d_in[12];
    const float* Wout = (const float*)d_in[13];
    const float* bout = (const float*)d_in[14];
    float* out = (float*)d_out;

    const int N = in_sizes[0] / LWN;
    const int P = in_sizes[2] / 4;

    int dev = 0;
    cudaGetDevice(&dev);
    int smCount = 148;
    cudaDeviceGetAttribute(&smCount, cudaDevAttrMultiProcessorCount, dev);
    int bpm = 1;
    cudaOccupancyMaxActiveBlocksPerMultiprocessor(&bpm, star_all, 256, 0);
    if (bpm < 1) bpm = 1;
    int grid = smCount * bpm;
    if (grid > MAXCTAS) grid = MAXCTAS;

    star_all<<<grid, 256>>>(xw, xi, tree, Ebu, Wz, Uz, bz, Wr, Ur, br,
                            Wh, Uh, bh, Wout, bout, out, N, P);
}

// round 5
// speedup vs baseline: 1.4039x; 1.4039x over previous
#include <cuda_runtime.h>
#include <math.h>

#define HDIM   512
#define LWN    32
#define VOCABC 5000
#define MAXLVL 20002
#define MAXCTAS 1024
#define NTOTC  40000
#define NPARC  20000
#define MAXTILES 24576

// ---------------- static device scratch ----------------
__device__ float g_Et[(size_t)VOCABC * HDIM];
__device__ float g_node_h[(size_t)NTOTC * HDIM];
__device__ float g_xe_par[(size_t)NPARC * HDIM];
__device__ float g_Wx[(size_t)NPARC * 3 * HDIM];
__device__ float g_mem[(size_t)NPARC * HDIM];
__device__ float g_zbuf[(size_t)NPARC * HDIM];
__device__ float g_mr[(size_t)NPARC * HDIM];
__device__ int   g_lvl[NTOTC];
__device__ int   g_order[NPARC];
__device__ int   g_slot[NPARC];
__device__ int   g_lvl_cnt[MAXLVL];
__device__ int   g_lvl_off[MAXLVL + 2];
__device__ int   g_lvl_cur[MAXLVL];
__device__ int   g_lvl_tb[MAXLVL];
__device__ int   g_lvl_shift[MAXLVL];
__device__ int   g_maxlvl;
__device__ int   g_mem_rdy[NPARC];
__device__ int   g_cnt1[MAXTILES];
__device__ int   g_cnt2[MAXTILES];
__device__ float g_part[(size_t)MAXCTAS * HDIM];
__device__ unsigned g_bar_cnt1[64 * 32];
__device__ unsigned g_bar_cnt2;
__device__ unsigned g_bar_gen;

// ---------------- two-level grid barrier (all CTAs co-resident) ----------------
__device__ __forceinline__ void gbar() {
    __syncthreads();
    if (threadIdx.x == 0) {
        __threadfence();
        const unsigned gen = *((volatile unsigned*)&g_bar_gen);
        const int grp  = blockIdx.x >> 4;
        const int ngrp = ((int)gridDim.x + 15) >> 4;
        const int gsz  = min(16, (int)gridDim.x - (grp << 4));
        if (atomicAdd(&g_bar_cnt1[grp * 32], 1u) == (unsigned)(gsz - 1)) {
            g_bar_cnt1[grp * 32] = 0;
            if (atomicAdd(&g_bar_cnt2, 1u) == (unsigned)(ngrp - 1)) {
                g_bar_cnt2 = 0;
                __threadfence();
                *((volatile unsigned*)&g_bar_gen) = gen + 1u;
            }
        }
        while (*((volatile unsigned*)&g_bar_gen) == gen) { __nanosleep(16); }
        __threadfence();
    }
    __syncthreads();
}

__device__ __forceinline__ float sigm(float x) { return 1.f / (1.f + __expf(-x)); }

// packed 2xfp32 FMA (Blackwell FFMA2) — bit-identical to two scalar fmaf
__device__ __forceinline__ void ffma2(float2& d, const float2 a, const float2 b) {
    unsigned long long& dd = reinterpret_cast<unsigned long long&>(d);
    const unsigned long long aa = *reinterpret_cast<const unsigned long long*>(&a);
    const unsigned long long bb = *reinterpret_cast<const unsigned long long*>(&b);
    asm("fma.rn.f32x2 %0, %1, %2, %0;" : "+l"(dd) : "l"(aa), "l"(bb));
}

// shared pool (floats): As [32*132] | Bs [32*68] | rid [128 ints]
#define POOL_AS   0
#define POOL_BS   (32 * 132)
#define POOL_RID  (POOL_BS + 32 * 68)
#define POOL_SIZE (POOL_RID + 128)

// ---------------- tiled fp32 GEMM (FFMA2, K-step 32) with fused epilogues ----------------
// MODE 0: Wx  = A@[Wz|Wr|Wh]^T + bias            (no flags)
// MODE 1: zr  = A(mem)@[Uz|Ur]^T; z->g_zbuf, r->g_mr=r*mem   (spin mem_rdy, bump cnt1)
// MODE 2: c   = A(mr)@Uh^T; GRU combine -> node_h            (spin cnt1==16, bump cnt2)
template<int TM, int MODE>
__device__ void run_gemm(float* pool, int M, const int* __restrict__ rowids,
                         const float* __restrict__ Asrc, int Nn,
                         const float* __restrict__ B0, const float* __restrict__ B1,
                         const float* __restrict__ B2,
                         const float* __restrict__ bz, const float* __restrict__ br,
                         const float* __restrict__ bh, int L, int cta, int ncta, int tb)
{
    constexpr int MR = (TM == 128) ? 8 : 2;
    constexpr int PR = MR / 2;
    constexpr int AST = TM + 4;
    float* AsP = pool + POOL_AS;
    float* BsP = pool + POOL_BS;
    int*   rid = (int*)(pool + POOL_RID);
#define AS_(k,m) AsP[(k) * AST + (m)]
#define BS_(k,m) BsP[(k) * 68 + (m)]

    const int tid = threadIdx.x;
    const int tx = tid & 15, ty = tid >> 4;
    const int li = tid >> 2;
    const int lk = (tid & 3) << 2;
    const int nMt = (M + TM - 1) / TM, nNt = Nn >> 6;
    const int nTiles = nMt * nNt;

    for (int tile = cta; tile < nTiles; tile += ncta) {
        const int mt = tile / nNt, nt = tile - mt * nNt;
        const int m0 = mt * TM, n0 = nt << 6;
        __syncthreads();
        if (tid < TM) {
            int rr = m0 + tid;
            rid[tid] = (rr < M) ? (rowids ? rowids[rr] : rr) : -1;
        }
        __syncthreads();

        if (MODE == 1) {
            if (tid < TM) {
                int p = rid[tid];
                if (p >= 0)
                    while (*((volatile int*)&g_mem_rdy[p]) == 0) __nanosleep(32);
            }
            __threadfence();
            __syncthreads();
        } else if (MODE == 2) {
            if (tid == 0)
                while (*((volatile int*)&g_cnt1[tb + mt]) < 16) __nanosleep(32);
            __threadfence();
            __syncthreads();
        }

        const float* Bbase = (n0 < 512) ? B0 : ((n0 < 1024) ? B1 : B2);
        const int nb = n0 & 511;
        const float* bRow = Bbase + (size_t)(nb + li) * HDIM;

        int ar0 = -1, ar1 = -1, arowk = 0;
        const float* aRow0 = Asrc;
        const float* aRow1 = Asrc;
        if (TM == 128) {
            ar0 = rid[li]; ar1 = rid[li + 64];
            aRow0 = Asrc + (size_t)(ar0 < 0 ? 0 : ar0) * HDIM;
            aRow1 = Asrc + (size_t)(ar1 < 0 ? 0 : ar1) * HDIM;
        } else {
            ar0 = rid[tid & 31];
            aRow0 = Asrc + (size_t)(ar0 < 0 ? 0 : ar0) * HDIM;
            arowk = (tid >> 5) << 2;   // 0..28
        }

        float2 acc[PR][4];
#pragma unroll
        for (int i = 0; i < PR; i++)
#pragma unroll
            for (int j = 0; j < 4; j++) acc[i][j] = make_float2(0.f, 0.f);

#pragma unroll 1
        for (int k0 = 0; k0 < HDIM; k0 += 32) {
            float4 a0 = make_float4(0,0,0,0), a1 = make_float4(0,0,0,0);
            float4 a2_ = make_float4(0,0,0,0), a3 = make_float4(0,0,0,0);
            if (TM == 128) {
                if (ar0 >= 0) {
                    a0 = *(const float4*)(aRow0 + k0 + lk);
                    a1 = *(const float4*)(aRow0 + k0 + 16 + lk);
                }
                if (ar1 >= 0) {
                    a2_ = *(const float4*)(aRow1 + k0 + lk);
                    a3  = *(const float4*)(aRow1 + k0 + 16 + lk);
                }
            } else {
                if (ar0 >= 0) a0 = *(const float4*)(aRow0 + k0 + arowk);
            }
            float4 b0 = *(const float4*)(bRow + k0 + lk);
            float4 b1 = *(const float4*)(bRow + k0 + 16 + lk);
            __syncthreads();
            if (TM == 128) {
                AS_(lk+0, li) = a0.x; AS_(lk+1, li) = a0.y;
                AS_(lk+2, li) = a0.z; AS_(lk+3, li) = a0.w;
                AS_(16+lk+0, li) = a1.x; AS_(16+lk+1, li) = a1.y;
                AS_(16+lk+2, li) = a1.z; AS_(16+lk+3, li) = a1.w;
                AS_(lk+0, 64+li) = a2_.x; AS_(lk+1, 64+li) = a2_.y;
                AS_(lk+2, 64+li) = a2_.z; AS_(lk+3, 64+li) = a2_.w;
                AS_(16+lk+0, 64+li) = a3.x; AS_(16+lk+1, 64+li) = a3.y;
                AS_(16+lk+2, 64+li) = a3.z; AS_(16+lk+3, 64+li) = a3.w;
            } else {
                const int rr = tid & 31;
                AS_(arowk+0, rr) = a0.x; AS_(arowk+1, rr) = a0.y;
                AS_(arowk+2, rr) = a0.z; AS_(arowk+3, rr) = a0.w;
            }
            BS_(lk+0, li) = b0.x; BS_(lk+1, li) = b0.y;
            BS_(lk+2, li) = b0.z; BS_(lk+3, li) = b0.w;
            BS_(16+lk+0, li) = b1.x; BS_(16+lk+1, li) = b1.y;
            BS_(16+lk+2, li) = b1.z; BS_(16+lk+3, li) = b1.w;
            __syncthreads();
#pragma unroll
            for (int kk = 0; kk < 32; kk++) {
                float4 b = *(const float4*)&BS_(kk, tx << 2);
                float2 bb0 = make_float2(b.x, b.x);
                float2 bb1 = make_float2(b.y, b.y);
                float2 bb2 = make_float2(b.z, b.z);
                float2 bb3 = make_float2(b.w, b.w);
                float2 a2v[PR];
                if (TM == 128) {
                    float4 t0 = *(const float4*)&AS_(kk, ty * MR);
                    a2v[0] = make_float2(t0.x, t0.y);
                    a2v[1] = make_float2(t0.z, t0.w);
                    float4 t1 = *(const float4*)&AS_(kk, ty * MR + 4);
                    a2v[2] = make_float2(t1.x, t1.y);
                    a2v[3] = make_float2(t1.z, t1.w);
                } else {
                    a2v[0] = *(const float2*)&AS_(kk, ty * 2);
                }
#pragma unroll
                for (int pr = 0; pr < PR; pr++) {
                    ffma2(acc[pr][0], a2v[pr], bb0);
                    ffma2(acc[pr][1], a2v[pr], bb1);
                    ffma2(acc[pr][2], a2v[pr], bb2);
                    ffma2(acc[pr][3], a2v[pr], bb3);
                }
            }
        }
        // epilogue
#pragma unroll
        for (int pr = 0; pr < PR; pr++) {
#pragma unroll
            for (int h = 0; h < 2; h++) {
                const int lrow = ty * MR + pr * 2 + h;
                const int p = rid[lrow];
                if (p < 0) continue;
#pragma unroll
                for (int j = 0; j < 4; j++) {
                    const int c = n0 + (tx << 2) + j;
                    const float a = h ? acc[pr][j].y : acc[pr][j].x;
                    if (MODE == 0) {
                        float bias = (c < 512) ? bz[c] : ((c < 1024) ? br[c-512] : bh[c-1024]);
                        g_Wx[(size_t)p*1536 + c] = a + bias;
                    } else if (MODE == 1) {
                        if (c < 512) {
                            g_zbuf[(size_t)p*HDIM + c] = sigm(a + g_Wx[(size_t)p*1536 + c]);
                        } else {
                            const int c2 = c - 512;
                            float r = sigm(a + g_Wx[(size_t)p*1536 + 512 + c2]);
                            g_mr[(size_t)p*HDIM + c2] = r * g_mem[(size_t)p*HDIM + c2];
                        }
                    } else {
                        float cc = tanhf(a + g_Wx[(size_t)p*1536 + 1024 + c]);
                        float z  = g_zbuf[(size_t)p*HDIM + c];
                        float mm = g_mem[(size_t)p*HDIM + c];
                        g_node_h[(size_t)(L + p)*HDIM + c] = z*mm + (1.f - z)*cc;
                    }
                }
            }
        }
        if (MODE >= 1) {
            __threadfence();
            __syncthreads();
            if (tid == 0) {
                if (MODE == 1) atomicAdd(&g_cnt1[tb + mt], 1);
                else           atomicAdd(&g_cnt2[tb + mt], 1);
            }
        }
    }
#undef AS_
#undef BS_
}

// ---------------- 5-layer star attention (dataflow), one warp per parent ----------------
__device__ void attn_level(int off, int cnt, const int* __restrict__ tree, int L)
{
    const int lane = threadIdx.x & 31;
    const int gw = (blockIdx.x * blockDim.x + threadIdx.x) >> 5;
    const int nw = (gridDim.x * blockDim.x) >> 5;
    for (int it = gw; it < cnt; it += nw) {
        const int p = g_order[off + it];
        // wait for children (lanes 0..3 each spin one child's tile counter)
        if (lane < 4) {
            int c = tree[p * 4 + lane];
            if (c >= L) {
                int lvc = g_lvl[c];
                int tl = g_lvl_tb[lvc] +
                         ((g_slot[c - L] - g_lvl_off[lvc]) >> g_lvl_shift[lvc]);
                while (*((volatile int*)&g_cnt2[tl]) < 8) __nanosleep(32);
            }
        }
        __syncwarp();
        __threadfence();

        unsigned mbglob = 0u;
#pragma unroll 1
        for (int half = 0; half < 2; half++) {
            const int cbase = half * 256 + lane * 8;
            float v[4][8];
            unsigned mb = 0u;
#pragma unroll
            for (int i = 0; i < 4; i++) {
                int c = tree[p * 4 + i];
                if (c >= 0) {
                    mb |= (1u << i);
                    const float4* hp = (const float4*)(g_node_h + (size_t)c*HDIM + cbase);
                    float4 a = hp[0], b = hp[1];
                    v[i][0]=a.x; v[i][1]=a.y; v[i][2]=a.z; v[i][3]=a.w;
                    v[i][4]=b.x; v[i][5]=b.y; v[i][6]=b.z; v[i][7]=b.w;
                } else {
#pragma unroll
                    for (int j = 0; j < 8; j++) v[i][j] = 0.f;
                }
            }
            mbglob = mb;
            const float denom = (float)max(__popc(mb), 1);
#pragma unroll 1
            for (int layer = 0; layer < 5; layer++) {
                float s[4][4];
#pragma unroll
                for (int i = 0; i < 4; i++)
#pragma unroll
                    for (int k = 0; k < 4; k++) {
                        float t = 0.f;
#pragma unroll
                        for (int j = 0; j < 8; j++) t += v[i][j] * v[k][j];
                        t += __shfl_xor_sync(0xffffffffu, t, 1);
                        t += __shfl_xor_sync(0xffffffffu, t, 2);
                        t += __shfl_xor_sync(0xffffffffu, t, 4);
                        s[i][k] = ((mb >> k) & 1u) ? t * 0.125f : -1e9f;
                    }
#pragma unroll
                for (int i = 0; i < 4; i++) {
                    float mx = fmaxf(fmaxf(s[i][0], s[i][1]), fmaxf(s[i][2], s[i][3]));
                    float e0 = __expf(s[i][0]-mx), e1 = __expf(s[i][1]-mx);
                    float e2 = __expf(s[i][2]-mx), e3 = __expf(s[i][3]-mx);
                    float inv = 1.f / (e0+e1+e2+e3);
                    s[i][0]=e0*inv; s[i][1]=e1*inv; s[i][2]=e2*inv; s[i][3]=e3*inv;
                }
                float o[4][8];
#pragma unroll
                for (int i = 0; i < 4; i++)
#pragma unroll
                    for (int j = 0; j < 8; j++)
                        o[i][j] = s[i][0]*v[0][j] + s[i][1]*v[1][j]
                                + s[i][2]*v[2][j] + s[i][3]*v[3][j];
#pragma unroll
                for (int i = 0; i < 4; i++)
#pragma unroll
                    for (int j = 0; j < 8; j++) v[i][j] = o[i][j];
            }
            float m8[8];
#pragma unroll
            for (int j = 0; j < 8; j++) {
                float t = 0.f;
#pragma unroll
                for (int i = 0; i < 4; i++) if ((mb >> i) & 1u) t += v[i][j];
                m8[j] = t / denom;
            }
            float4* mp = (float4*)(g_mem + (size_t)p*HDIM + cbase);
            mp[0] = make_float4(m8[0], m8[1], m8[2], m8[3]);
            mp[1] = make_float4(m8[4], m8[5], m8[6], m8[7]);
        }
        (void)mbglob;
        __threadfence();
        if (lane == 0) atomicExch(&g_mem_rdy[p], 1);
        __syncwarp();
    }
}

// ---------------- the persistent kernel ----------------
extern "C" __global__ void __launch_bounds__(256, 2) star_all(
    const float* __restrict__ xw, const int* __restrict__ xi, const int* __restrict__ tree,
    const float* __restrict__ Ebu,
    const float* __restrict__ Wz, const float* __restrict__ Uz, const float* __restrict__ bz,
    const float* __restrict__ Wr, const float* __restrict__ Ur, const float* __restrict__ br,
    const float* __restrict__ Wh, const float* __restrict__ Uh, const float* __restrict__ bh,
    const float* __restrict__ Wout, const float* __restrict__ bout,
    float* __restrict__ out, int N, int P)
{
    __shared__ __align__(16) float s_pool[POOL_SIZE];
    const int L = N - P;
    const int tid = threadIdx.x;
    const int gtid = blockIdx.x * blockDim.x + tid;
    const int nthreads = gridDim.x * blockDim.x;

    // ---- P0: init flags/levels/counters + transpose embedding ----
    for (int n = gtid; n < N; n += nthreads) g_lvl[n] = (n < L) ? 0 : -1;
    for (int i = gtid; i < MAXLVL; i += nthreads) g_lvl_cnt[i] = 0;
    for (int i = gtid; i < MAXTILES; i += nthreads) { g_cnt1[i] = 0; g_cnt2[i] = 0; }
    for (int i = gtid; i < NPARC; i += nthreads) g_mem_rdy[i] = 0;
    if (gtid == 0) g_maxlvl = 0;
    {
        const int tot = HDIM * VOCABC;
        for (int e = gtid; e < tot; e += nthreads) {
            int h = e / VOCABC, v = e - h * VOCABC;
            g_Et[(size_t)v * HDIM + h] = Ebu[e];
        }
    }
    gbar();

    // ---- P1: embedding xe = sum_l Et[idx]*w ----
    {
        const int c0 = tid, c1 = tid + 256;
        for (int n = blockIdx.x; n < N; n += gridDim.x) {
            const int4*   ip4 = (const int4*)(xi + (size_t)n * LWN);
            const float4* wp4 = (const float4*)(xw + (size_t)n * LWN);
            float a0 = 0.f, a1 = 0.f;
#pragma unroll
            for (int q = 0; q < 8; q++) {
                int4 iv = ip4[q]; float4 wv = wp4[q];
                const float* e0 = g_Et + (size_t)iv.x * HDIM;
                const float* e1 = g_Et + (size_t)iv.y * HDIM;
                const float* e2 = g_Et + (size_t)iv.z * HDIM;
                const float* e3 = g_Et + (size_t)iv.w * HDIM;
                a0 += e0[c0]*wv.x + e1[c0]*wv.y + e2[c0]*wv.z + e3[c0]*wv.w;
                a1 += e0[c1]*wv.x + e1[c1]*wv.y + e2[c1]*wv.z + e3[c1]*wv.w;
            }
            float* dst = (n < L) ? (g_node_h + (size_t)n * HDIM)
                                 : (g_xe_par + (size_t)(n - L) * HDIM);
            dst[c0] = a0; dst[c1] = a1;
        }
    }
    gbar();

    // ---- P2: level discovery (dataflow spin) ----
    for (int p = gtid; p < P; p += nthreads) {
        int lv = 0;
#pragma unroll
        for (int i = 0; i < 4; i++) {
            int c = tree[p * 4 + i];
            if (c >= 0) {
                int cl;
                if (c < L) cl = 0;
                else {
                    while ((cl = *((volatile int*)&g_lvl[c])) < 0) { __nanosleep(32); }
                }
                lv = max(lv, cl);
            }
        }
        lv += 1;
        *((volatile int*)&g_lvl[L + p]) = lv;
        atomicAdd(&g_lvl_cnt[lv], 1);
        atomicMax(&g_maxlvl, lv);
    }
    gbar();

    // ---- P3: Wx GEMM on blocks>0; block0 thread0: level prefix + tile bases ----
    if (blockIdx.x == 0) {
        if (tid == 0) {
            int ml = g_maxlvl;
            int run = 0, tbr = 0;
            for (int lv = 1; lv <= ml; lv++) {
                g_lvl_off[lv] = run;
                g_lvl_cur[lv] = run;
                int c = g_lvl_cnt[lv];
                int sh = (c >= 1024) ? 7 : 5;
                g_lvl_shift[lv] = sh;
                g_lvl_tb[lv] = tbr;
                tbr += (c + (1 << sh) - 1) >> sh;
                run += c;
            }
            g_lvl_off[ml + 1] = run;
        }
        __syncthreads();
    } else {
        run_gemm<128, 0>(s_pool, P, nullptr, g_xe_par, 1536, Wz, Wr, Wh,
                         bz, br, bh, L, blockIdx.x - 1, gridDim.x - 1, 0);
    }
    gbar();

    // ---- P4: scatter parents into level-ordered array (+ inverse) ----
    for (int p = gtid; p < P; p += nthreads) {
        int lv = g_lvl[L + p];
        int slot = atomicAdd(&g_lvl_cur[lv], 1);
        g_order[slot] = p;
        g_slot[p] = slot;
    }
    gbar();

    // ---- dataflow level loop (no grid barriers) ----
    const int maxlvl = g_maxlvl;
    for (int lv = 1; lv <= maxlvl; lv++) {
        const int off = g_lvl_off[lv];
        const int cnt = g_lvl_off[lv + 1] - off;
        if (cnt == 0) continue;
        const int tb = g_lvl_tb[lv];
        attn_level(off, cnt, tree, L);
        __syncthreads();
        if (g_lvl_shift[lv] == 7) {
            run_gemm<128, 1>(s_pool, cnt, g_order + off, g_mem, 1024, Uz, Ur, nullptr,
                             nullptr, nullptr, nullptr, L, blockIdx.x, gridDim.x, tb);
            run_gemm<128, 2>(s_pool, cnt, g_order + off, g_mr, 512, Uh, nullptr, nullptr,
                             nullptr, nullptr, nullptr, L, blockIdx.x, gridDim.x, tb);
        } else {
            run_gemm<32, 1>(s_pool, cnt, g_order + off, g_mem, 1024, Uz, Ur, nullptr,
                            nullptr, nullptr, nullptr, L, blockIdx.x, gridDim.x, tb);
            run_gemm<32, 2>(s_pool, cnt, g_order + off, g_mr, 512, Uh, nullptr, nullptr,
                            nullptr, nullptr, nullptr, L, blockIdx.x, gridDim.x, tb);
        }
    }
    gbar();

    // ---- P5: per-CTA column max over parents ----
    {
        const int rpc = (P + gridDim.x - 1) / gridDim.x;
        const int r0 = blockIdx.x * rpc;
        const int r1 = min(r0 + rpc, P);
        const int c0 = tid, c1 = tid + 256;
        float v0 = -3.4e38f, v1 = -3.4e38f;
        for (int r = r0; r < r1; r++) {
            const float* row = g_node_h + (size_t)(L + r) * HDIM;
            v0 = fmaxf(v0, row[c0]);
            v1 = fmaxf(v1, row[c1]);
        }
        g_part[(size_t)blockIdx.x * HDIM + c0] = v0;
        g_part[(size_t)blockIdx.x * HDIM + c1] = v1;
    }
    gbar();

    // ---- P6: block 0: reduce, matvec, softmax ----
    if (blockIdx.x == 0) {
        float* sfinal = s_pool;
        float* slog   = s_pool + HDIM;
        const int c0 = tid, c1 = tid + 256;
        float v0 = -3.4e38f, v1 = -3.4e38f;
        for (int g = 0; g < (int)gridDim.x; g++) {
            v0 = fmaxf(v0, g_part[(size_t)g * HDIM + c0]);
            v1 = fmaxf(v1, g_part[(size_t)g * HDIM + c1]);
        }
        sfinal[c0] = v0; sfinal[c1] = v1;
        __syncthreads();
        const int w = tid >> 5, lane = tid & 31;
        if (w < 4) {
            float t = 0.f;
#pragma unroll
            for (int j = 0; j < 16; j++) {
                int c = lane * 16 + j;
                t += Wout[w * HDIM + c] * sfinal[c];
            }
#pragma unroll
            for (int d = 16; d > 0; d >>= 1) t += __shfl_xor_sync(0xffffffffu, t, d);
            if (lane == 0) slog[w] = t + bout[w];
        }
        __syncthreads();
        if (tid == 0) {
            float mx = fmaxf(fmaxf(slog[0], slog[1]), fmaxf(slog[2], slog[3]));
            float e0 = __expf(slog[0]-mx), e1 = __expf(slog[1]-mx);
            float e2 = __expf(slog[2]-mx), e3 = __expf(slog[3]-mx);
            float inv = 1.f / (e0+e1+e2+e3);
            out[0] = e0*inv; out[1] = e1*inv; out[2] = e2*inv; out[3] = e3*inv;
        }
    }
}

extern "C" void kernel_launch(void* const* d_in, const int* in_sizes, int n_in,
                              void* d_out, int out_size) {
    const float* xw   = (const float*)d_in[0];
    const int*   xi   = (const int*)  d_in[1];
    const int*   tree = (const int*)  d_in[2];
    const float* Ebu  = (const float*)d_in[3];
    const float* Wz   = (const float*)d_in[4];
    const float* Uz   = (const float*)d_in[5];
    const float* bz   = (const float*)d_in[6];
    const float* Wr   = (const float*)d_in[7];
    const float* Ur   = (const float*)d_in[8];
    const float* br   = (const float*)d_in[9];
    const float* Wh   = (const float*)d_in[10];
    const float* Uh   = (const float*)d_in[11];
    const float* bh   = (const float*)d_in[12];
    const float* Wout = (const float*)d_in[13];
    const float* bout = (const float*)d_in[14];
    float* out = (float*)d_out;

    const int N = in_sizes[0] / LWN;
    const int P = in_sizes[2] / 4;

    int dev = 0;
    cudaGetDevice(&dev);
    int smCount = 148;
    cudaDeviceGetAttribute(&smCount, cudaDevAttrMultiProcessorCount, dev);
    int bpm = 1;
    cudaOccupancyMaxActiveBlocksPerMultiprocessor(&bpm, star_all, 256, 0);
    if (bpm < 1) bpm = 1;
    int grid = smCount * bpm;
    if (grid > MAXCTAS) grid = MAXCTAS;

    star_all<<<grid, 256>>>(xw, xi, tree, Ebu, Wz, Uz, bz, Wr, Ur, br,
                            Wh, Uh, bh, Wout, bout, out, N, P);
}

// round 9
// speedup vs baseline: 2.1487x; 1.5305x over previous
#include <cuda_runtime.h>
#include <cuda_bf16.h>
#include <math.h>
#include <stdint.h>

#define HDIM   512
#define LWN    32
#define VOCABC 5000
#define MAXLVL 20002
#define MAXCTAS 1024
#define NTOTC  40000
#define NPARC  20000

// smem stage layout (bytes): Ah[128*80] Al[128*80] Bh[64*80] Bl[64*80]
#define STAGE   30720
#define A_L_OFF 10240
#define B_H_OFF 20480
#define B_L_OFF 25600
#define RID_OFF 61440
#define SMEM_REQ (61440 + 512)

// ---------------- static device scratch ----------------
__device__ float g_Et[(size_t)VOCABC * HDIM];
__device__ float g_node_h[(size_t)NTOTC * HDIM];
__device__ float g_Wx[(size_t)NPARC * 3 * HDIM];
__device__ float g_mem[(size_t)NPARC * HDIM];
__device__ float g_zbuf[(size_t)NPARC * HDIM];
__device__ __nv_bfloat16 g_xeh[(size_t)NPARC * HDIM];
__device__ __nv_bfloat16 g_xel[(size_t)NPARC * HDIM];
__device__ __nv_bfloat16 g_memh[(size_t)NPARC * HDIM];
__device__ __nv_bfloat16 g_meml[(size_t)NPARC * HDIM];
__device__ __nv_bfloat16 g_mrh[(size_t)NPARC * HDIM];
__device__ __nv_bfloat16 g_mrl[(size_t)NPARC * HDIM];
__device__ __nv_bfloat16 g_Wbh[(size_t)1536 * HDIM];
__device__ __nv_bfloat16 g_Wbl[(size_t)1536 * HDIM];
__device__ __nv_bfloat16 g_Uzh[(size_t)1024 * HDIM];
__device__ __nv_bfloat16 g_Uzl[(size_t)1024 * HDIM];
__device__ __nv_bfloat16 g_Uhh[(size_t)512 * HDIM];
__device__ __nv_bfloat16 g_Uhl[(size_t)512 * HDIM];
__device__ float g_bcat[1536];
__device__ int   g_lvl[NTOTC];
__device__ int   g_order[NPARC];
__device__ int   g_lvl_cnt[MAXLVL];
__device__ int   g_lvl_off[MAXLVL + 2];
__device__ int   g_lvl_cur[MAXLVL];
__device__ int   g_maxlvl;
__device__ float g_part[(size_t)MAXCTAS * HDIM];
__device__ unsigned g_bar_cnt1[64 * 32];
__device__ unsigned g_bar_cnt2;
__device__ unsigned g_bar_gen;

// ---------------- two-level grid barrier (all CTAs co-resident) ----------------
__device__ __forceinline__ void gbar() {
    __syncthreads();
    if (threadIdx.x == 0) {
        __threadfence();
        const unsigned gen = *((volatile unsigned*)&g_bar_gen);
        const int grp  = blockIdx.x >> 4;
        const int ngrp = ((int)gridDim.x + 15) >> 4;
        const int gsz  = min(16, (int)gridDim.x - (grp << 4));
        if (atomicAdd(&g_bar_cnt1[grp * 32], 1u) == (unsigned)(gsz - 1)) {
            g_bar_cnt1[grp * 32] = 0;
            if (atomicAdd(&g_bar_cnt2, 1u) == (unsigned)(ngrp - 1)) {
                g_bar_cnt2 = 0;
                __threadfence();
                *((volatile unsigned*)&g_bar_gen) = gen + 1u;
            }
        }
        while (*((volatile unsigned*)&g_bar_gen) == gen) { __nanosleep(16); }
        __threadfence();
    }
    __syncthreads();
}

__device__ __forceinline__ float sigm(float x) { return 1.f / (1.f + __expf(-x)); }

// ---------------- PTX helpers (all sm_80-era, no arch suffix) ----------------
__device__ __forceinline__ uint32_t s2u(const void* p) {
    uint32_t a;
    asm("{ .reg .u64 t; cvta.to.shared.u64 t, %1; cvt.u32.u64 %0, t; }" : "=r"(a) : "l"(p));
    return a;
}
__device__ __forceinline__ void ldmx4(uint32_t* r, uint32_t addr) {
    asm volatile("ldmatrix.sync.aligned.m8n8.x4.shared.b16 {%0,%1,%2,%3}, [%4];"
        : "=r"(r[0]), "=r"(r[1]), "=r"(r[2]), "=r"(r[3]) : "r"(addr));
}
__device__ __forceinline__ void ldmx2(uint32_t* r, uint32_t addr) {
    asm volatile("ldmatrix.sync.aligned.m8n8.x2.shared.b16 {%0,%1}, [%2];"
        : "=r"(r[0]), "=r"(r[1]) : "r"(addr));
}
__device__ __forceinline__ void hmma(float* d, const uint32_t* a, const uint32_t* b) {
    asm volatile("mma.sync.aligned.m16n8k16.row.col.f32.bf16.bf16.f32 "
        "{%0,%1,%2,%3}, {%4,%5,%6,%7}, {%8,%9}, {%0,%1,%2,%3};"
        : "+f"(d[0]), "+f"(d[1]), "+f"(d[2]), "+f"(d[3])
        : "r"(a[0]), "r"(a[1]), "r"(a[2]), "r"(a[3]), "r"(b[0]), "r"(b[1]));
}
__device__ __forceinline__ void cpa16(uint32_t dst, const __nv_bfloat16* src) {
    asm volatile("cp.async.cg.shared.global [%0], [%1], 16;"
                 :: "r"(dst), "l"(__cvta_generic_to_global(src)));
}
__device__ __forceinline__ void cpa_commit() {
    asm volatile("cp.async.commit_group;" ::: "memory");
}
__device__ __forceinline__ void cpa_wait1() {
    asm volatile("cp.async.wait_group 1;" ::: "memory");
}
__device__ __forceinline__ void cpa_wait0() {
    asm volatile("cp.async.wait_group 0;" ::: "memory");
}

__device__ __forceinline__ void bsplit(float x, __nv_bfloat16* h, __nv_bfloat16* l) {
    __nv_bfloat16 hh = __float2bfloat16(x);
    *h = hh;
    *l = __float2bfloat16(x - __bfloat162float(hh));
}

// ---------------- bf16-split tensor GEMM (mma.sync, cp.async 2-stage) ----------------
// D[M,Nn] = A[M,512] @ B[Nn,512]^T with A=Ah+Al, B=Bh+Bl (drop Al*Bl).
// MODE 0: g_Wx = D + bcat   MODE 1: z/r gates, mr=r*mem   MODE 2: GRU -> node_h
template<int MODE>
__device__ void tgemm(char* smem, uint32_t sb, int M, const int* __restrict__ rowids,
                      const __nv_bfloat16* __restrict__ Ah, const __nv_bfloat16* __restrict__ Al,
                      const __nv_bfloat16* __restrict__ Bh, const __nv_bfloat16* __restrict__ Bl,
                      int Nn, int L, int cta, int ncta)
{
    const int tid = threadIdx.x;
    const int lane = tid & 31, wid = tid >> 5;
    const int wm = wid & 3, wn = wid >> 2;          // 4x2 warp grid
    int* rid = (int*)(smem + RID_OFF);
    const int nMt = (M + 127) >> 7, nNt = Nn >> 6;
    const int nTiles = nMt * nNt;

    // cp.async thread roles
    const int arow = tid >> 1, ahalf = tid & 1;     // A: 2 thr/row, 32B each
    const int brow = tid >> 2, bseg = tid & 3;      // B: 4 thr/row, 16B each

    // ldmatrix per-lane offsets (within stage)
    const uint32_t aLM = (uint32_t)((wm * 32 + (lane & 15)) * 80 + (lane >> 4) * 16);
    const uint32_t bLM = (uint32_t)(B_H_OFF + (wn * 32 + (lane & 7)) * 80 + ((lane >> 3) & 1) * 16);

    for (int tile = cta; tile < nTiles; tile += ncta) {
        const int mt = tile / nNt, nt = tile - mt * nNt;
        const int m0 = mt << 7, n0 = nt << 6;
        __syncthreads();
        if (tid < 128) {
            int rr = m0 + tid;
            rid[tid] = (rr < M) ? (rowids ? rowids[rr] : rr) : -1;
        }
        __syncthreads();

        const int ap = rid[arow];
        const __nv_bfloat16* aph = Ah + (size_t)(ap < 0 ? 0 : ap) * HDIM + ahalf * 16;
        const __nv_bfloat16* apl = Al + (size_t)(ap < 0 ? 0 : ap) * HDIM + ahalf * 16;
        const __nv_bfloat16* bph = Bh + (size_t)(n0 + brow) * HDIM + bseg * 8;
        const __nv_bfloat16* bpl = Bl + (size_t)(n0 + brow) * HDIM + bseg * 8;
        const uint32_t adst = sb + arow * 80 + ahalf * 32;
        const uint32_t bdst = sb + brow * 80 + bseg * 16;

        float acc[2][4][4];
#pragma unroll
        for (int i = 0; i < 2; i++)
#pragma unroll
            for (int j = 0; j < 4; j++)
#pragma unroll
                for (int e = 0; e < 4; e++) acc[i][j][e] = 0.f;

        // issue chunk 0
        {
            cpa16(adst, aph); cpa16(adst + 16, aph + 8);
            cpa16(adst + A_L_OFF, apl); cpa16(adst + A_L_OFF + 16, apl + 8);
            cpa16(bdst + B_H_OFF, bph);
            cpa16(bdst + B_L_OFF, bpl);
            cpa_commit();
        }

#pragma unroll 1
        for (int kc = 0; kc < 16; kc++) {
            const int s = kc & 1;
            if (kc + 1 < 16) {
                const int ke = (kc + 1) * 32;
                const uint32_t so = (uint32_t)((kc + 1) & 1) * STAGE;
                cpa16(adst + so, aph + ke); cpa16(adst + so + 16, aph + ke + 8);
                cpa16(adst + so + A_L_OFF, apl + ke);
                cpa16(adst + so + A_L_OFF + 16, apl + ke + 8);
                cpa16(bdst + so + B_H_OFF, bph + ke);
                cpa16(bdst + so + B_L_OFF, bpl + ke);
                cpa_commit();
                cpa_wait1();
            } else {
                cpa_wait0();
            }
            __syncthreads();
            const uint32_t sbase = sb + (uint32_t)s * STAGE;
#pragma unroll
            for (int ks = 0; ks < 2; ks++) {
                uint32_t ahf[2][4], alf[2][4], bhf[4][2], blf[4][2];
#pragma unroll
                for (int tm = 0; tm < 2; tm++) {
                    uint32_t aa = sbase + aLM + tm * (16 * 80) + ks * 32;
                    ldmx4(ahf[tm], aa);
                    ldmx4(alf[tm], aa + A_L_OFF);
                }
#pragma unroll
                for (int tn = 0; tn < 4; tn++) {
                    uint32_t ba = sbase + bLM + tn * (8 * 80) + ks * 32;
                    ldmx2(bhf[tn], ba);
                    ldmx2(blf[tn], ba + (B_L_OFF - B_H_OFF));
                }
#pragma unroll
                for (int tm = 0; tm < 2; tm++)
#pragma unroll
                    for (int tn = 0; tn < 4; tn++) {
                        hmma(acc[tm][tn], ahf[tm], bhf[tn]);
                        hmma(acc[tm][tn], ahf[tm], blf[tn]);
                        hmma(acc[tm][tn], alf[tm], bhf[tn]);
                    }
            }
            __syncthreads();
        }

        // epilogue: fragment (e0,e1)=(r,c),(r,c+1); (e2,e3)=(r+8,c),(r+8,c+1)
#pragma unroll
        for (int tm = 0; tm < 2; tm++)
#pragma unroll
            for (int e = 0; e < 4; e += 2) {
                const int m = wm * 32 + tm * 16 + (lane >> 2) + ((e >= 2) ? 8 : 0);
                const int p = rid[m];
                if (p < 0) continue;
#pragma unroll
                for (int tn = 0; tn < 4; tn++)
#pragma unroll
                    for (int u = 0; u < 2; u++) {
                        const int c = n0 + wn * 32 + tn * 8 + (lane & 3) * 2 + u;
                        const float v = acc[tm][tn][e + u];
                        if (MODE == 0) {
                            g_Wx[(size_t)p * 1536 + c] = v + g_bcat[c];
                        } else if (MODE == 1) {
                            if (c < 512) {
                                g_zbuf[(size_t)p * HDIM + c] =
                                    sigm(v + g_Wx[(size_t)p * 1536 + c]);
                            } else {
                                const int c2 = c - 512;
                                float r = sigm(v + g_Wx[(size_t)p * 1536 + 512 + c2]);
                                float mr = r * g_mem[(size_t)p * HDIM + c2];
                                bsplit(mr, &g_mrh[(size_t)p * HDIM + c2],
                                           &g_mrl[(size_t)p * HDIM + c2]);
                            }
                        } else {
                            float cc = tanhf(v + g_Wx[(size_t)p * 1536 + 1024 + c]);
                            float z  = g_zbuf[(size_t)p * HDIM + c];
                            float mm = g_mem[(size_t)p * HDIM + c];
                            g_node_h[(size_t)(L + p) * HDIM + c] = z * mm + (1.f - z) * cc;
                        }
                    }
            }
    }
}

// ---------------- 5-layer star attention, one warp per (parent, half) ----------------
__device__ void attn_phase(int off, int B, const int* __restrict__ tree)
{
    const int lane = threadIdx.x & 31;
    const int gw = (blockIdx.x * blockDim.x + threadIdx.x) >> 5;
    const int nw = (gridDim.x * blockDim.x) >> 5;
    for (int item = gw; item < 2 * B; item += nw) {
        const int p = g_order[off + (item >> 1)];
        const int half = item & 1;
        const int cbase = half * 256 + lane * 8;
        float v[4][8];
        unsigned mb = 0u;
#pragma unroll
        for (int i = 0; i < 4; i++) {
            int c = tree[p * 4 + i];
            if (c >= 0) {
                mb |= (1u << i);
                const float4* hp = (const float4*)(g_node_h + (size_t)c * HDIM + cbase);
                float4 a = hp[0], b = hp[1];
                v[i][0]=a.x; v[i][1]=a.y; v[i][2]=a.z; v[i][3]=a.w;
                v[i][4]=b.x; v[i][5]=b.y; v[i][6]=b.z; v[i][7]=b.w;
            } else {
#pragma unroll
                for (int j = 0; j < 8; j++) v[i][j] = 0.f;
            }
        }
        const float denom = (float)max(__popc(mb), 1);
#pragma unroll 1
        for (int layer = 0; layer < 5; layer++) {
            float s[4][4];
#pragma unroll
            for (int i = 0; i < 4; i++)
#pragma unroll
                for (int k = 0; k < 4; k++) {
                    float t = 0.f;
#pragma unroll
                    for (int j = 0; j < 8; j++) t += v[i][j] * v[k][j];
                    t += __shfl_xor_sync(0xffffffffu, t, 1);
                    t += __shfl_xor_sync(0xffffffffu, t, 2);
                    t += __shfl_xor_sync(0xffffffffu, t, 4);
                    s[i][k] = ((mb >> k) & 1u) ? t * 0.125f : -1e9f;
                }
#pragma unroll
            for (int i = 0; i < 4; i++) {
                float mx = fmaxf(fmaxf(s[i][0], s[i][1]), fmaxf(s[i][2], s[i][3]));
                float e0 = __expf(s[i][0]-mx), e1 = __expf(s[i][1]-mx);
                float e2 = __expf(s[i][2]-mx), e3 = __expf(s[i][3]-mx);
                float inv = 1.f / (e0+e1+e2+e3);
                s[i][0]=e0*inv; s[i][1]=e1*inv; s[i][2]=e2*inv; s[i][3]=e3*inv;
            }
            float o[4][8];
#pragma unroll
            for (int i = 0; i < 4; i++)
#pragma unroll
                for (int j = 0; j < 8; j++)
                    o[i][j] = s[i][0]*v[0][j] + s[i][1]*v[1][j]
                            + s[i][2]*v[2][j] + s[i][3]*v[3][j];
#pragma unroll
            for (int i = 0; i < 4; i++)
#pragma unroll
                for (int j = 0; j < 8; j++) v[i][j] = o[i][j];
        }
        float m8[8];
#pragma unroll
        for (int j = 0; j < 8; j++) {
            float t = 0.f;
#pragma unroll
            for (int i = 0; i < 4; i++) if ((mb >> i) & 1u) t += v[i][j];
            m8[j] = t / denom;
        }
        float4* mp = (float4*)(g_mem + (size_t)p * HDIM + cbase);
        mp[0] = make_float4(m8[0], m8[1], m8[2], m8[3]);
        mp[1] = make_float4(m8[4], m8[5], m8[6], m8[7]);
#pragma unroll
        for (int j = 0; j < 8; j++)
            bsplit(m8[j], &g_memh[(size_t)p * HDIM + cbase + j],
                          &g_meml[(size_t)p * HDIM + cbase + j]);
    }
}

// ---------------- the persistent kernel ----------------
extern "C" __global__ void __launch_bounds__(256, 2) star_all(
    const float* __restrict__ xw, const int* __restrict__ xi, const int* __restrict__ tree,
    const float* __restrict__ Ebu,
    const float* __restrict__ Wz, const float* __restrict__ Uz, const float* __restrict__ bz,
    const float* __restrict__ Wr, const float* __restrict__ Ur, const float* __restrict__ br,
    const float* __restrict__ Wh, const float* __restrict__ Uh, const float* __restrict__ bh,
    const float* __restrict__ Wout, const float* __restrict__ bout,
    float* __restrict__ out, int N, int P)
{
    extern __shared__ char smem[];
    const uint32_t sb = s2u(smem);

    const int L = N - P;
    const int tid = threadIdx.x;
    const int gtid = blockIdx.x * blockDim.x + tid;
    const int nthreads = gridDim.x * blockDim.x;

    // ---- P0: init + transpose embedding + weight bf16 split ----
    for (int n = gtid; n < N; n += nthreads) g_lvl[n] = (n < L) ? 0 : -1;
    for (int i = gtid; i < MAXLVL; i += nthreads) g_lvl_cnt[i] = 0;
    if (gtid == 0) g_maxlvl = 0;
    {
        const int tot = HDIM * VOCABC;
        for (int e = gtid; e < tot; e += nthreads) {
            int h = e / VOCABC, v = e - h * VOCABC;
            g_Et[(size_t)v * HDIM + h] = Ebu[e];
        }
    }
    for (int e = gtid; e < 1536 * HDIM; e += nthreads) {
        int r = e >> 9, c = e & 511;
        float w = (r < 512) ? Wz[r * 512 + c] : (r < 1024) ? Wr[(r - 512) * 512 + c]
                                              : Wh[(r - 1024) * 512 + c];
        bsplit(w, &g_Wbh[e], &g_Wbl[e]);
    }
    for (int e = gtid; e < 1024 * HDIM; e += nthreads) {
        int r = e >> 9, c = e & 511;
        float w = (r < 512) ? Uz[r * 512 + c] : Ur[(r - 512) * 512 + c];
        bsplit(w, &g_Uzh[e], &g_Uzl[e]);
    }
    for (int e = gtid; e < 512 * HDIM; e += nthreads)
        bsplit(Uh[e], &g_Uhh[e], &g_Uhl[e]);
    for (int i = gtid; i < 1536; i += nthreads)
        g_bcat[i] = (i < 512) ? bz[i] : (i < 1024) ? br[i - 512] : bh[i - 1024];
    gbar();

    // ---- P1: embedding ----
    {
        const int c0 = tid, c1 = tid + 256;
        for (int n = blockIdx.x; n < N; n += gridDim.x) {
            const int4*   ip4 = (const int4*)(xi + (size_t)n * LWN);
            const float4* wp4 = (const float4*)(xw + (size_t)n * LWN);
            float a0 = 0.f, a1 = 0.f;
#pragma unroll
            for (int q = 0; q < 8; q++) {
                int4 iv = ip4[q]; float4 wv = wp4[q];
                const float* e0 = g_Et + (size_t)iv.x * HDIM;
                const float* e1 = g_Et + (size_t)iv.y * HDIM;
                const float* e2 = g_Et + (size_t)iv.z * HDIM;
                const float* e3 = g_Et + (size_t)iv.w * HDIM;
                a0 += e0[c0]*wv.x + e1[c0]*wv.y + e2[c0]*wv.z + e3[c0]*wv.w;
                a1 += e0[c1]*wv.x + e1[c1]*wv.y + e2[c1]*wv.z + e3[c1]*wv.w;
            }
            if (n < L) {
                g_node_h[(size_t)n * HDIM + c0] = a0;
                g_node_h[(size_t)n * HDIM + c1] = a1;
            } else {
                const size_t pp = (size_t)(n - L) * HDIM;
                bsplit(a0, &g_xeh[pp + c0], &g_xel[pp + c0]);
                bsplit(a1, &g_xeh[pp + c1], &g_xel[pp + c1]);
            }
        }
    }
    gbar();

    // ---- P2: level discovery ----
    for (int p = gtid; p < P; p += nthreads) {
        int lv = 0;
#pragma unroll
        for (int i = 0; i < 4; i++) {
            int c = tree[p * 4 + i];
            if (c >= 0) {
                int cl;
                if (c < L) cl = 0;
                else { while ((cl = *((volatile int*)&g_lvl[c])) < 0) { __nanosleep(32); } }
                lv = max(lv, cl);
            }
        }
        lv += 1;
        *((volatile int*)&g_lvl[L + p]) = lv;
        atomicAdd(&g_lvl_cnt[lv], 1);
        atomicMax(&g_maxlvl, lv);
    }
    gbar();

    // ---- P3: Wx tensor GEMM (blocks>0) + level prefix (block0) ----
    if (blockIdx.x == 0) {
        if (tid == 0) {
            int ml = g_maxlvl;
            int run = 0;
            for (int lv = 1; lv <= ml; lv++) {
                g_lvl_off[lv] = run;
                g_lvl_cur[lv] = run;
                run += g_lvl_cnt[lv];
            }
            g_lvl_off[ml + 1] = run;
        }
        __syncthreads();
    } else {
        tgemm<0>(smem, sb, P, nullptr, g_xeh, g_xel, g_Wbh, g_Wbl,
                 1536, L, blockIdx.x - 1, gridDim.x - 1);
    }
    gbar();

    // ---- P4: scatter parents into level order ----
    for (int p = gtid; p < P; p += nthreads) {
        int lv = g_lvl[L + p];
        int slot = atomicAdd(&g_lvl_cur[lv], 1);
        g_order[slot] = p;
    }
    gbar();

    // ---- level loop ----
    const int maxlvl = g_maxlvl;
    for (int lv = 1; lv <= maxlvl; lv++) {
        const int off = g_lvl_off[lv];
        const int cnt = g_lvl_off[lv + 1] - off;
        if (cnt == 0) continue;
        attn_phase(off, cnt, tree);
        gbar();
        tgemm<1>(smem, sb, cnt, g_order + off, g_memh, g_meml,
                 g_Uzh, g_Uzl, 1024, L, blockIdx.x, gridDim.x);
        gbar();
        tgemm<2>(smem, sb, cnt, g_order + off, g_mrh, g_mrl,
                 g_Uhh, g_Uhl, 512, L, blockIdx.x, gridDim.x);
        gbar();
    }

    // ---- P5: per-CTA column max over parents ----
    {
        const int rpc = (P + gridDim.x - 1) / gridDim.x;
        const int r0 = blockIdx.x * rpc;
        const int r1 = min(r0 + rpc, P);
        const int c0 = tid, c1 = tid + 256;
        float v0 = -3.4e38f, v1 = -3.4e38f;
        for (int r = r0; r < r1; r++) {
            const float* row = g_node_h + (size_t)(L + r) * HDIM;
            v0 = fmaxf(v0, row[c0]);
            v1 = fmaxf(v1, row[c1]);
        }
        g_part[(size_t)blockIdx.x * HDIM + c0] = v0;
        g_part[(size_t)blockIdx.x * HDIM + c1] = v1;
    }
    gbar();

    // ---- P6: block 0: reduce, matvec, softmax ----
    if (blockIdx.x == 0) {
        float* sfinal = (float*)smem;
        float* slog   = sfinal + HDIM;
        const int c0 = tid, c1 = tid + 256;
        float v0 = -3.4e38f, v1 = -3.4e38f;
        for (int g = 0; g < (int)gridDim.x; g++) {
            v0 = fmaxf(v0, g_part[(size_t)g * HDIM + c0]);
            v1 = fmaxf(v1, g_part[(size_t)g * HDIM + c1]);
        }
        sfinal[c0] = v0; sfinal[c1] = v1;
        __syncthreads();
        const int w = tid >> 5, lane = tid & 31;
        if (w < 4) {
            float t = 0.f;
#pragma unroll
            for (int j = 0; j < 16; j++) {
                int c = lane * 16 + j;
                t += Wout[w * HDIM + c] * sfinal[c];
            }
#pragma unroll
            for (int d = 16; d > 0; d >>= 1) t += __shfl_xor_sync(0xffffffffu, t, d);
            if (lane == 0) slog[w] = t + bout[w];
        }
        __syncthreads();
        if (tid == 0) {
            float mx = fmaxf(fmaxf(slog[0], slog[1]), fmaxf(slog[2], slog[3]));
            float e0 = __expf(slog[0]-mx), e1 = __expf(slog[1]-mx);
            float e2 = __expf(slog[2]-mx), e3 = __expf(slog[3]-mx);
            float inv = 1.f / (e0+e1+e2+e3);
            out[0] = e0*inv; out[1] = e1*inv; out[2] = e2*inv; out[3] = e3*inv;
        }
    }
}

extern "C" void kernel_launch(void* const* d_in, const int* in_sizes, int n_in,
                              void* d_out, int out_size) {
    const float* xw   = (const float*)d_in[0];
    const int*   xi   = (const int*)  d_in[1];
    const int*   tree = (const int*)  d_in[2];
    const float* Ebu  = (const float*)d_in[3];
    const float* Wz   = (const float*)d_in[4];
    const float* Uz   = (const float*)d_in[5];
    const float* bz   = (const float*)d_in[6];
    const float* Wr   = (const float*)d_in[7];
    const float* Ur   = (const float*)d_in[8];
    const float* br   = (const float*)d_in[9];
    const float* Wh   = (const float*)d_in[10];
    const float* Uh   = (const float*)d_in[11];
    const float* bh   = (const float*)d_in[12];
    const float* Wout = (const float*)d_in[13];
    const float* bout = (const float*)d_in[14];
    float* out = (float*)d_out;

    const int N = in_sizes[0] / LWN;
    const int P = in_sizes[2] / 4;

    int dev = 0;
    cudaGetDevice(&dev);
    int smCount = 148;
    cudaDeviceGetAttribute(&smCount, cudaDevAttrMultiProcessorCount, dev);

    cudaFuncSetAttribute(star_all, cudaFuncAttributeMaxDynamicSharedMemorySize, SMEM_REQ);
    int bpm = 1;
    cudaOccupancyMaxActiveBlocksPerMultiprocessor(&bpm, star_all, 256, SMEM_REQ);
    if (bpm < 1) bpm = 1;
    int grid = smCount * bpm;
    if (grid > MAXCTAS) grid = MAXCTAS;

    star_all<<<grid, 256, SMEM_REQ>>>(xw, xi, tree, Ebu, Wz, Uz, bz, Wr, Ur, br,
                                      Wh, Uh, bh, Wout, bout, out, N, P);
}